// round 13
// baseline (speedup 1.0000x reference)
#include <cuda_runtime.h>
#include <cuda_fp16.h>
#include <math.h>
#include <stdint.h>

// ---------------- problem constants ----------------
#define NTOK  16384
#define CDIM  768
#define FDIM  3072
#define NEXP  8
#define NPAIR (NTOK * 2)

// ---------------- scratch (static device arrays) ----------------
__device__ int    g_count[NEXP];
__device__ int    g_bucket[NEXP * NTOK];
__device__ float  g_wt[NPAIR];
__device__ __half g_xh[(size_t)NTOK * CDIM];          // x in fp16
__device__ __half g_w1t[(size_t)NEXP * FDIM * CDIM];  // w1^T fp16 [E][F][C] (K contig)
__device__ __half g_w2t[(size_t)NEXP * CDIM * FDIM];  // w2^T fp16 [E][C][F]
__device__ __half g_h[(size_t)NPAIR * FDIM];          // gelu(x@w1+b1) fp16
__device__ float  g_y[(size_t)NPAIR * CDIM];          // w*(h@w2+b2) per pair

// ---------------- helpers ----------------
__device__ __forceinline__ float gelu_f(float x) {
    return 0.5f * x * (1.0f + erff(x * 0.70710678118654752440f));
}
__device__ __forceinline__ uint32_t sw128(uint32_t o) { return o ^ ((o >> 3) & 0x70); }

__device__ __forceinline__ void cp16s(uint32_t saddr, const void* g) {
    asm volatile("cp.async.cg.shared.global [%0], [%1], 16;" :: "r"(saddr), "l"(g));
}

__device__ __forceinline__ void ldm_x4(uint32_t r[4], uint32_t addr) {
    asm volatile("ldmatrix.sync.aligned.m8n8.x4.shared.b16 {%0,%1,%2,%3}, [%4];"
                 : "=r"(r[0]), "=r"(r[1]), "=r"(r[2]), "=r"(r[3]) : "r"(addr));
}

__device__ __forceinline__ void mma16816(float c[4], const uint32_t a[4], const uint32_t* b) {
    asm volatile(
        "mma.sync.aligned.m16n8k16.row.col.f32.f16.f16.f32 "
        "{%0,%1,%2,%3},{%4,%5,%6,%7},{%8,%9},{%0,%1,%2,%3};"
        : "+f"(c[0]), "+f"(c[1]), "+f"(c[2]), "+f"(c[3])
        : "r"(a[0]), "r"(a[1]), "r"(a[2]), "r"(a[3]), "r"(b[0]), "r"(b[1]));
}

// ---------------- kernel: init ----------------
__global__ void init_kernel() {
    if (threadIdx.x < NEXP) g_count[threadIdx.x] = 0;
}

// ---------------- kernel: router + fused x->fp16 conversion ----------------
__global__ void router_kernel(const float* __restrict__ x, const float* __restrict__ rw) {
    __shared__ float srw[NEXP * CDIM];
    int tid = threadIdx.x;
    for (int j = tid; j < NEXP * CDIM; j += 256) srw[j] = rw[j];
    __syncthreads();

    int warp = tid >> 5, lane = tid & 31;
    int t = blockIdx.x * 8 + warp;

    float xv[24];
#pragma unroll
    for (int j = 0; j < 24; j++) xv[j] = x[(size_t)t * CDIM + lane + 32 * j];

#pragma unroll
    for (int j = 0; j < 24; j++)
        g_xh[(size_t)t * CDIM + lane + 32 * j] = __float2half(xv[j]);

    float logit[NEXP];
#pragma unroll
    for (int e = 0; e < NEXP; e++) {
        float s = 0.0f;
#pragma unroll
        for (int j = 0; j < 24; j++) s += xv[j] * srw[e * CDIM + lane + 32 * j];
#pragma unroll
        for (int o = 16; o > 0; o >>= 1) s += __shfl_xor_sync(0xffffffffu, s, o);
        logit[e] = s;
    }

    if (lane == 0) {
        int e0 = 0; float l0 = logit[0];
#pragma unroll
        for (int e = 1; e < NEXP; e++)
            if (logit[e] > l0) { l0 = logit[e]; e0 = e; }
        int e1 = (e0 == 0) ? 1 : 0; float l1 = logit[e1];
#pragma unroll
        for (int e = 0; e < NEXP; e++)
            if (e != e0 && logit[e] > l1) { l1 = logit[e]; e1 = e; }

        float d = expf(l1 - l0);
        float w0 = 1.0f / (1.0f + d);
        float w1 = d / (1.0f + d);

        int p0 = 2 * t, p1 = 2 * t + 1;
        g_wt[p0] = w0;
        g_wt[p1] = w1;
        int pos0 = atomicAdd(&g_count[e0], 1);
        g_bucket[e0 * NTOK + pos0] = p0;
        int pos1 = atomicAdd(&g_count[e1], 1);
        g_bucket[e1 * NTOK + pos1] = p1;
    }
}

// ---------------- kernel: transpose + convert weights (v2) ----------------
// in: [E][R][S] fp32 -> out: [E][S][R] fp16.  Tile: 128 r-rows x 32 s-cols.
template <int WSEL>
__global__ void transpose_h(const float* __restrict__ in, int R, int S) {
    __half* out = (WSEL == 1) ? g_w1t : g_w2t;
    __shared__ float tile[32][129];
    int e = blockIdx.z;
    const float* I = in + (size_t)e * R * S;
    __half* O = out + (size_t)e * R * S;
    int s0 = blockIdx.x * 32, r0 = blockIdx.y * 128;
    int tx = threadIdx.x, ty = threadIdx.y;   // block (32, 8)
#pragma unroll
    for (int k = 0; k < 16; k++) {
        int row = ty + 8 * k;                 // 0..127
        tile[tx][row] = I[(size_t)(r0 + row) * S + s0 + tx];
    }
    __syncthreads();
    int u  = ty * 32 + tx;                    // 0..255
    int rr = (u & 63) * 2;                    // 0..126
#pragma unroll
    for (int k = 0; k < 8; k++) {
        int sy = (u >> 6) + 4 * k;            // 0..31
        __half2 h2 = __floats2half2_rn(tile[sy][rr], tile[sy][rr + 1]);
        *reinterpret_cast<__half2*>(O + (size_t)(s0 + sy) * R + r0 + rr) = h2;
    }
}

// ---------------- fp16 HMMA MoE GEMM (R6 mainloop, n-fastest raster) -------
// PHASE 1: g_h[pair] = gelu(x[tok] @ w1[e] + b1[e])       (K=768,  N=3072)
// PHASE 2: g_y[pair] = w_pair * (g_h[pair] @ w2[e] + b2)  (K=3072, N=768)
// Raster: blockIdx.x = n-tile (fastest) so one m-tile's n-sweep is concurrent
// -> A rows fetched from DRAM once, served from L2; weight slab (4.7MB/expert)
// is L2-resident regardless.
#define BM   128
#define BN   128
#define BKH  64                           // halves of K per chunk (128B rows)
#define NST  3
#define A_BYTES (BM * 128)
#define B_BYTES (BN * 128)
#define STAGE_BYTES (A_BYTES + B_BYTES)   // 32768
#define SMEM_DYN (NST * STAGE_BYTES + 1024)
#define EPI_STRIDE 272                    // fp16 tile row stride; 16B-aligned (17*16)

template <int PHASE>
__global__ void __launch_bounds__(256, 2) moe_gemm(const float* __restrict__ bias) {
    constexpr int KD = (PHASE == 1) ? CDIM : FDIM;
    constexpr int ND = (PHASE == 1) ? FDIM : CDIM;
    constexpr int KT = KD / BKH;          // 12 or 48

    const int e   = blockIdx.z;
    const int cnt = g_count[e];
    const int m0  = blockIdx.y * BM;      // y = m-tile
    if (m0 >= cnt) return;
    const int n0  = blockIdx.x * BN;      // x = n-tile (fastest -> A reuse in L2)

    extern __shared__ char dsm[];
    uint32_t sb0;
    asm("{ .reg .u64 t; cvta.to.shared.u64 t, %1; cvt.u32.u64 %0, t; }" : "=r"(sb0) : "l"(dsm));
    const uint32_t sbase = (sb0 + 1023) & ~1023u;
    char* smal = dsm + (sbase - sb0);     // aligned smem base (C++ view)

    __shared__ int   sPair[BM];
    __shared__ float sW[BM];

    const int tid  = threadIdx.x;
    const int wid  = tid >> 5;
    const int lane = tid & 31;

    if (tid < BM) {
        int pr = g_bucket[e * NTOK + min(m0 + tid, cnt - 1)];
        sPair[tid] = pr;
        sW[tid] = g_wt[pr];
    }
    __syncthreads();

    const __half* Ag = (PHASE == 1) ? g_xh : g_h;
    const __half* We = ((PHASE == 1) ? g_w1t : g_w2t)
                       + (size_t)e * KD * ND + (size_t)n0 * KD;

    // ---- per-thread precomputed copy sources / swizzled dests ----
    const int crow = tid >> 3, cch = tid & 7;          // 32 rows per pass, 8x16B per row
    const __half* aSrc[4]; const __half* bSrc[4];
    uint32_t aDst[4], bDst[4];
#pragma unroll
    for (int q = 0; q < 4; q++) {
        int r = crow + q * 32;
        int pr = sPair[r];
        aSrc[q] = Ag + ((PHASE == 1) ? (size_t)(pr >> 1) * CDIM : (size_t)pr * FDIM) + cch * 8;
        bSrc[q] = We + (size_t)r * KD + cch * 8;
        aDst[q] = sw128((uint32_t)(r * 128 + cch * 16));
        bDst[q] = sw128((uint32_t)(r * 128 + cch * 16)) + A_BYTES;
    }

    auto load_chunk = [&](int kt) {
        const uint32_t base = sbase + (kt % NST) * STAGE_BYTES;
        const int koff = kt * BKH;
#pragma unroll
        for (int q = 0; q < 4; q++) cp16s(base + aDst[q], aSrc[q] + koff);
#pragma unroll
        for (int q = 0; q < 4; q++) cp16s(base + bDst[q], bSrc[q] + koff);
        asm volatile("cp.async.commit_group;");
    };

    // ---- per-thread ldmatrix address precompute ----
    const int wm = wid >> 2, wn = wid & 3;             // 2x4 warp grid, warp tile 64x32
    const int ahi = lane >> 4;
    const int bhi = (lane >> 3) & 1;
    uint32_t arel[4]; int axr[4];
#pragma unroll
    for (int mi = 0; mi < 4; mi++) {
        int r = wm * 64 + mi * 16 + (lane & 15);
        arel[mi] = r * 128;
        axr[mi] = r & 7;
    }
    uint32_t brel[2]; int bxr[2];
#pragma unroll
    for (int nj = 0; nj < 2; nj++) {
        int r = wn * 32 + nj * 16 + ((lane >> 4) << 3) + (lane & 7);
        brel[nj] = r * 128;
        bxr[nj] = r & 7;
    }

    float acc[4][4][4];
#pragma unroll
    for (int i = 0; i < 4; i++)
#pragma unroll
        for (int j = 0; j < 4; j++)
#pragma unroll
            for (int r = 0; r < 4; r++) acc[i][j][r] = 0.0f;

    load_chunk(0);
    load_chunk(1);

#pragma unroll 1
    for (int kt = 0; kt < KT; kt++) {
        if (kt + 2 < KT) asm volatile("cp.async.wait_group 1;");
        else             asm volatile("cp.async.wait_group 0;");
        __syncthreads();
        if (kt + 2 < KT) load_chunk(kt + 2);   // stage (kt+2)%3 freed by this barrier

        const uint32_t ab = sbase + (kt % NST) * STAGE_BYTES;
        const uint32_t bb = ab + A_BYTES;
#pragma unroll
        for (int ks = 0; ks < 4; ks++) {
            uint32_t a[4][4], b[2][4];
#pragma unroll
            for (int mi = 0; mi < 4; mi++)
                ldm_x4(a[mi], ab + arel[mi] + ((uint32_t)((ks * 2 + ahi) ^ axr[mi]) << 4));
#pragma unroll
            for (int nj = 0; nj < 2; nj++)
                ldm_x4(b[nj], bb + brel[nj] + ((uint32_t)((ks * 2 + bhi) ^ bxr[nj]) << 4));
#pragma unroll
            for (int mi = 0; mi < 4; mi++)
#pragma unroll
                for (int ni = 0; ni < 4; ni++)
                    mma16816(acc[mi][ni], a[mi], &b[ni >> 1][(ni & 1) * 2]);
        }
    }

    // ---------------- epilogue ----------------
    const int gid = lane >> 2, tig = lane & 3;
    const float* bptr = bias + (size_t)e * ND;

    if (PHASE == 1) {
        // Stage fp16 tile in smem (stage 0/1 region free after last chunk).
#pragma unroll
        for (int mi = 0; mi < 4; mi++) {
#pragma unroll
            for (int half = 0; half < 2; half++) {
                int rl = wm * 64 + mi * 16 + gid + half * 8;
                char* rowp = smal + rl * EPI_STRIDE;
#pragma unroll
                for (int ni = 0; ni < 4; ni++) {
                    int cl = wn * 32 + ni * 8 + 2 * tig;      // col in tile
                    int n  = n0 + cl;
                    float v0 = gelu_f(acc[mi][ni][half * 2 + 0] + bptr[n]);
                    float v1 = gelu_f(acc[mi][ni][half * 2 + 1] + bptr[n + 1]);
                    *reinterpret_cast<__half2*>(rowp + cl * 2) = __floats2half2_rn(v0, v1);
                }
            }
        }
        __syncthreads();
        // Coalesced 16B stores: 2048 chunks of 16B, 8 per thread.
#pragma unroll
        for (int k = 0; k < 8; k++) {
            int id  = tid + k * 256;
            int row = id >> 4, seg = id & 15;
            if (m0 + row < cnt) {
                uint4 v = *reinterpret_cast<uint4*>(smal + row * EPI_STRIDE + seg * 16);
                int pr = sPair[row];
                *reinterpret_cast<uint4*>(g_h + (size_t)pr * FDIM + n0 + seg * 8) = v;
            }
        }
    } else {
#pragma unroll
        for (int mi = 0; mi < 4; mi++) {
#pragma unroll
            for (int half = 0; half < 2; half++) {
                int rl = wm * 64 + mi * 16 + gid + half * 8;
                if (m0 + rl < cnt) {
                    int pr = sPair[rl];
                    float wgt  = sW[rl];
                    float* dst = g_y + (size_t)pr * CDIM;
#pragma unroll
                    for (int ni = 0; ni < 4; ni++) {
                        int n = n0 + wn * 32 + ni * 8 + 2 * tig;
                        float2 v;
                        v.x = wgt * (acc[mi][ni][half * 2 + 0] + bptr[n]);
                        v.y = wgt * (acc[mi][ni][half * 2 + 1] + bptr[n + 1]);
                        *reinterpret_cast<float2*>(dst + n) = v;
                    }
                }
            }
        }
    }
}

// ---------------- kernel: combine pairs -> out ----------------
__global__ void combine_kernel(float* __restrict__ out) {
    int i = blockIdx.x * blockDim.x + threadIdx.x;
    const int n4 = NTOK * (CDIM / 4);
    if (i >= n4) return;
    int t = i / (CDIM / 4), c = i % (CDIM / 4);
    float4 a = ((const float4*)(g_y + (size_t)(2 * t) * CDIM))[c];
    float4 b = ((const float4*)(g_y + (size_t)(2 * t + 1) * CDIM))[c];
    float4 r;
    r.x = a.x + b.x;
    r.y = a.y + b.y;
    r.z = a.z + b.z;
    r.w = a.w + b.w;
    ((float4*)out)[i] = r;
}

// ---------------- launch ----------------
extern "C" void kernel_launch(void* const* d_in, const int* in_sizes, int n_in,
                              void* d_out, int out_size) {
    (void)in_sizes; (void)n_in; (void)out_size;
    const float* x  = (const float*)d_in[0];
    const float* rw = (const float*)d_in[1];
    const float* w1 = (const float*)d_in[2];
    const float* b1 = (const float*)d_in[3];
    const float* w2 = (const float*)d_in[4];
    const float* b2 = (const float*)d_in[5];
    float* out = (float*)d_out;

    cudaFuncSetAttribute(moe_gemm<1>, cudaFuncAttributeMaxDynamicSharedMemorySize, SMEM_DYN);
    cudaFuncSetAttribute(moe_gemm<2>, cudaFuncAttributeMaxDynamicSharedMemorySize, SMEM_DYN);

    init_kernel<<<1, 32>>>();
    router_kernel<<<NTOK / 8, 256>>>(x, rw);
    transpose_h<1><<<dim3(FDIM / 32, CDIM / 128, NEXP), dim3(32, 8)>>>(w1, CDIM, FDIM);
    transpose_h<2><<<dim3(CDIM / 32, FDIM / 128, NEXP), dim3(32, 8)>>>(w2, FDIM, CDIM);

    moe_gemm<1><<<dim3(FDIM / BN, NTOK / BM, NEXP), 256, SMEM_DYN>>>(b1);
    moe_gemm<2><<<dim3(CDIM / BN, NTOK / BM, NEXP), 256, SMEM_DYN>>>(b2);

    combine_kernel<<<(NTOK * (CDIM / 4) + 255) / 256, 256>>>(out);
}

// round 14
// speedup vs baseline: 1.0149x; 1.0149x over previous
#include <cuda_runtime.h>
#include <cuda_fp16.h>
#include <math.h>
#include <stdint.h>

// ---------------- problem constants ----------------
#define NTOK  16384
#define CDIM  768
#define FDIM  3072
#define NEXP  8
#define NPAIR (NTOK * 2)

// ---------------- scratch (static device arrays) ----------------
__device__ int    g_count[NEXP];
__device__ int    g_bucket[NEXP * NTOK];
__device__ float  g_wt[NPAIR];
__device__ __half g_xh[(size_t)NTOK * CDIM];          // x in fp16
__device__ __half g_w1t[(size_t)NEXP * FDIM * CDIM];  // w1^T fp16 [E][F][C] (K contig)
__device__ __half g_w2t[(size_t)NEXP * CDIM * FDIM];  // w2^T fp16 [E][C][F]
__device__ __half g_h[(size_t)NPAIR * FDIM];          // gelu(x@w1+b1) fp16
__device__ __half g_yh[(size_t)NPAIR * CDIM];         // w*(h@w2+b2) per pair, fp16

// ---------------- helpers ----------------
__device__ __forceinline__ float gelu_f(float x) {
    return 0.5f * x * (1.0f + erff(x * 0.70710678118654752440f));
}
__device__ __forceinline__ uint32_t sw128(uint32_t o) { return o ^ ((o >> 3) & 0x70); }

__device__ __forceinline__ void cp16s(uint32_t saddr, const void* g) {
    asm volatile("cp.async.cg.shared.global [%0], [%1], 16;" :: "r"(saddr), "l"(g));
}

__device__ __forceinline__ void ldm_x4(uint32_t r[4], uint32_t addr) {
    asm volatile("ldmatrix.sync.aligned.m8n8.x4.shared.b16 {%0,%1,%2,%3}, [%4];"
                 : "=r"(r[0]), "=r"(r[1]), "=r"(r[2]), "=r"(r[3]) : "r"(addr));
}

__device__ __forceinline__ void mma16816(float c[4], const uint32_t a[4], const uint32_t* b) {
    asm volatile(
        "mma.sync.aligned.m16n8k16.row.col.f32.f16.f16.f32 "
        "{%0,%1,%2,%3},{%4,%5,%6,%7},{%8,%9},{%0,%1,%2,%3};"
        : "+f"(c[0]), "+f"(c[1]), "+f"(c[2]), "+f"(c[3])
        : "r"(a[0]), "r"(a[1]), "r"(a[2]), "r"(a[3]), "r"(b[0]), "r"(b[1]));
}

// ---------------- kernel: init ----------------
__global__ void init_kernel() {
    if (threadIdx.x < NEXP) g_count[threadIdx.x] = 0;
}

// ---------------- kernel: fused prolog ----------------
// blocks [0, 2048)            : router + x->fp16 conversion
// blocks [2048, 6656)         : transpose w1 -> g_w1t  (R=CDIM, S=FDIM)
// blocks [6656, 11264)        : transpose w2 -> g_w2t  (R=FDIM, S=CDIM)
#define PRO_RTR  2048
#define PRO_T1   4608          // (FDIM/32=96) * (CDIM/128=6) * 8
#define PRO_T2   4608          // (CDIM/32=24) * (FDIM/128=24) * 8

__device__ __forceinline__ void transpose_body(
    const float* __restrict__ I, __half* __restrict__ O,
    int R, int S, int s0, int r0, float* tile /* [32][129] */, int tid)
{
    int tx = tid & 31, ty = tid >> 5;
#pragma unroll
    for (int k = 0; k < 16; k++) {
        int row = ty + 8 * k;                 // 0..127
        tile[tx * 129 + row] = I[(size_t)(r0 + row) * S + s0 + tx];
    }
    __syncthreads();
    int rr = (tid & 63) * 2;                  // 0..126
#pragma unroll
    for (int k = 0; k < 8; k++) {
        int sy = (tid >> 6) + 4 * k;          // 0..31
        __half2 h2 = __floats2half2_rn(tile[sy * 129 + rr], tile[sy * 129 + rr + 1]);
        *reinterpret_cast<__half2*>(O + (size_t)(s0 + sy) * R + r0 + rr) = h2;
    }
}

__global__ void prolog_kernel(const float* __restrict__ x,  const float* __restrict__ rw,
                              const float* __restrict__ w1, const float* __restrict__ w2) {
    __shared__ float smem[NEXP * CDIM];       // 24KB; transpose aliases first 16.5KB
    const int b   = blockIdx.x;
    const int tid = threadIdx.x;

    if (b < PRO_RTR) {
        // ---- router + fused x->fp16 ----
        for (int j = tid; j < NEXP * CDIM; j += 256) smem[j] = rw[j];
        __syncthreads();

        int warp = tid >> 5, lane = tid & 31;
        int t = b * 8 + warp;

        float xv[24];
#pragma unroll
        for (int j = 0; j < 24; j++) xv[j] = x[(size_t)t * CDIM + lane + 32 * j];
#pragma unroll
        for (int j = 0; j < 24; j++)
            g_xh[(size_t)t * CDIM + lane + 32 * j] = __float2half(xv[j]);

        float logit[NEXP];
#pragma unroll
        for (int e = 0; e < NEXP; e++) {
            float s = 0.0f;
#pragma unroll
            for (int j = 0; j < 24; j++) s += xv[j] * smem[e * CDIM + lane + 32 * j];
#pragma unroll
            for (int o = 16; o > 0; o >>= 1) s += __shfl_xor_sync(0xffffffffu, s, o);
            logit[e] = s;
        }

        if (lane == 0) {
            int e0 = 0; float l0 = logit[0];
#pragma unroll
            for (int e = 1; e < NEXP; e++)
                if (logit[e] > l0) { l0 = logit[e]; e0 = e; }
            int e1 = (e0 == 0) ? 1 : 0; float l1 = logit[e1];
#pragma unroll
            for (int e = 0; e < NEXP; e++)
                if (e != e0 && logit[e] > l1) { l1 = logit[e]; e1 = e; }

            float d = expf(l1 - l0);
            float w0 = 1.0f / (1.0f + d);
            float w1w = d / (1.0f + d);

            int p0 = 2 * t, p1 = 2 * t + 1;
            g_wt[p0] = w0;
            g_wt[p1] = w1w;
            int pos0 = atomicAdd(&g_count[e0], 1);
            g_bucket[e0 * NTOK + pos0] = p0;
            int pos1 = atomicAdd(&g_count[e1], 1);
            g_bucket[e1 * NTOK + pos1] = p1;
        }
    } else if (b < PRO_RTR + PRO_T1) {
        // ---- transpose w1: [E][CDIM][FDIM] fp32 -> [E][FDIM][CDIM] fp16 ----
        int bb = b - PRO_RTR;
        int sx = bb % (FDIM / 32);            // 0..95
        int ry = (bb / (FDIM / 32)) % (CDIM / 128);
        int e  = bb / ((FDIM / 32) * (CDIM / 128));
        transpose_body(w1 + (size_t)e * CDIM * FDIM, g_w1t + (size_t)e * CDIM * FDIM,
                       CDIM, FDIM, sx * 32, ry * 128, smem, tid);
    } else {
        // ---- transpose w2: [E][FDIM][CDIM] fp32 -> [E][CDIM][FDIM] fp16 ----
        int bb = b - PRO_RTR - PRO_T1;
        int sx = bb % (CDIM / 32);            // 0..23
        int ry = (bb / (CDIM / 32)) % (FDIM / 128);
        int e  = bb / ((CDIM / 32) * (FDIM / 128));
        transpose_body(w2 + (size_t)e * FDIM * CDIM, g_w2t + (size_t)e * FDIM * CDIM,
                       FDIM, CDIM, sx * 32, ry * 128, smem, tid);
    }
}

// ---------------- fp16 HMMA MoE GEMM (frozen R6 mainloop) ------------------
// PHASE 1: g_h[pair]  = gelu(x[tok] @ w1[e] + b1[e])      (K=768,  N=3072)
// PHASE 2: g_yh[pair] = w_pair * (g_h[pair] @ w2[e] + b2) (K=3072, N=768)
#define BM   128
#define BN   128
#define BKH  64                           // halves of K per chunk (128B rows)
#define NST  3
#define A_BYTES (BM * 128)
#define B_BYTES (BN * 128)
#define STAGE_BYTES (A_BYTES + B_BYTES)   // 32768
#define SMEM_DYN (NST * STAGE_BYTES + 1024)
#define EPI_STRIDE 272                    // fp16 tile row stride; 16B-aligned (17*16)

template <int PHASE>
__global__ void __launch_bounds__(256, 2) moe_gemm(const float* __restrict__ bias) {
    constexpr int KD = (PHASE == 1) ? CDIM : FDIM;
    constexpr int ND = (PHASE == 1) ? FDIM : CDIM;
    constexpr int KT = KD / BKH;          // 12 or 48

    const int e   = blockIdx.z;
    const int cnt = g_count[e];
    const int m0  = blockIdx.y * BM;      // y = m-tile
    if (m0 >= cnt) return;
    const int n0  = blockIdx.x * BN;      // x = n-tile

    extern __shared__ char dsm[];
    uint32_t sb0;
    asm("{ .reg .u64 t; cvta.to.shared.u64 t, %1; cvt.u32.u64 %0, t; }" : "=r"(sb0) : "l"(dsm));
    const uint32_t sbase = (sb0 + 1023) & ~1023u;
    char* smal = dsm + (sbase - sb0);     // aligned smem base (C++ view)

    __shared__ int   sPair[BM];
    __shared__ float sW[BM];

    const int tid  = threadIdx.x;
    const int wid  = tid >> 5;
    const int lane = tid & 31;

    if (tid < BM) {
        int pr = g_bucket[e * NTOK + min(m0 + tid, cnt - 1)];
        sPair[tid] = pr;
        sW[tid] = g_wt[pr];
    }
    __syncthreads();

    const __half* Ag = (PHASE == 1) ? g_xh : g_h;
    const __half* We = ((PHASE == 1) ? g_w1t : g_w2t)
                       + (size_t)e * KD * ND + (size_t)n0 * KD;

    // ---- per-thread precomputed copy sources / swizzled dests ----
    const int crow = tid >> 3, cch = tid & 7;          // 32 rows per pass, 8x16B per row
    const __half* aSrc[4]; const __half* bSrc[4];
    uint32_t aDst[4], bDst[4];
#pragma unroll
    for (int q = 0; q < 4; q++) {
        int r = crow + q * 32;
        int pr = sPair[r];
        aSrc[q] = Ag + ((PHASE == 1) ? (size_t)(pr >> 1) * CDIM : (size_t)pr * FDIM) + cch * 8;
        bSrc[q] = We + (size_t)r * KD + cch * 8;
        aDst[q] = sw128((uint32_t)(r * 128 + cch * 16));
        bDst[q] = sw128((uint32_t)(r * 128 + cch * 16)) + A_BYTES;
    }

    auto load_chunk = [&](int kt) {
        const uint32_t base = sbase + (kt % NST) * STAGE_BYTES;
        const int koff = kt * BKH;
#pragma unroll
        for (int q = 0; q < 4; q++) cp16s(base + aDst[q], aSrc[q] + koff);
#pragma unroll
        for (int q = 0; q < 4; q++) cp16s(base + bDst[q], bSrc[q] + koff);
        asm volatile("cp.async.commit_group;");
    };

    // ---- per-thread ldmatrix address precompute ----
    const int wm = wid >> 2, wn = wid & 3;             // 2x4 warp grid, warp tile 64x32
    const int ahi = lane >> 4;
    const int bhi = (lane >> 3) & 1;
    uint32_t arel[4]; int axr[4];
#pragma unroll
    for (int mi = 0; mi < 4; mi++) {
        int r = wm * 64 + mi * 16 + (lane & 15);
        arel[mi] = r * 128;
        axr[mi] = r & 7;
    }
    uint32_t brel[2]; int bxr[2];
#pragma unroll
    for (int nj = 0; nj < 2; nj++) {
        int r = wn * 32 + nj * 16 + ((lane >> 4) << 3) + (lane & 7);
        brel[nj] = r * 128;
        bxr[nj] = r & 7;
    }

    float acc[4][4][4];
#pragma unroll
    for (int i = 0; i < 4; i++)
#pragma unroll
        for (int j = 0; j < 4; j++)
#pragma unroll
            for (int r = 0; r < 4; r++) acc[i][j][r] = 0.0f;

    load_chunk(0);
    load_chunk(1);

#pragma unroll 1
    for (int kt = 0; kt < KT; kt++) {
        if (kt + 2 < KT) asm volatile("cp.async.wait_group 1;");
        else             asm volatile("cp.async.wait_group 0;");
        __syncthreads();
        if (kt + 2 < KT) load_chunk(kt + 2);   // stage (kt+2)%3 freed by this barrier

        const uint32_t ab = sbase + (kt % NST) * STAGE_BYTES;
        const uint32_t bb = ab + A_BYTES;
#pragma unroll
        for (int ks = 0; ks < 4; ks++) {
            uint32_t a[4][4], b[2][4];
#pragma unroll
            for (int mi = 0; mi < 4; mi++)
                ldm_x4(a[mi], ab + arel[mi] + ((uint32_t)((ks * 2 + ahi) ^ axr[mi]) << 4));
#pragma unroll
            for (int nj = 0; nj < 2; nj++)
                ldm_x4(b[nj], bb + brel[nj] + ((uint32_t)((ks * 2 + bhi) ^ bxr[nj]) << 4));
#pragma unroll
            for (int mi = 0; mi < 4; mi++)
#pragma unroll
                for (int ni = 0; ni < 4; ni++)
                    mma16816(acc[mi][ni], a[mi], &b[ni >> 1][(ni & 1) * 2]);
        }
    }

    // ---------------- epilogue ----------------
    const int gid = lane >> 2, tig = lane & 3;
    const float* bptr = bias + (size_t)e * ND;

    if (PHASE == 1) {
        // Stage fp16 tile in smem, then 16B coalesced stores.
#pragma unroll
        for (int mi = 0; mi < 4; mi++) {
#pragma unroll
            for (int half = 0; half < 2; half++) {
                int rl = wm * 64 + mi * 16 + gid + half * 8;
                char* rowp = smal + rl * EPI_STRIDE;
#pragma unroll
                for (int ni = 0; ni < 4; ni++) {
                    int cl = wn * 32 + ni * 8 + 2 * tig;      // col in tile
                    int n  = n0 + cl;
                    float v0 = gelu_f(acc[mi][ni][half * 2 + 0] + bptr[n]);
                    float v1 = gelu_f(acc[mi][ni][half * 2 + 1] + bptr[n + 1]);
                    *reinterpret_cast<__half2*>(rowp + cl * 2) = __floats2half2_rn(v0, v1);
                }
            }
        }
        __syncthreads();
#pragma unroll
        for (int k = 0; k < 8; k++) {
            int id  = tid + k * 256;
            int row = id >> 4, seg = id & 15;
            if (m0 + row < cnt) {
                uint4 v = *reinterpret_cast<uint4*>(smal + row * EPI_STRIDE + seg * 16);
                int pr = sPair[row];
                *reinterpret_cast<uint4*>(g_h + (size_t)pr * FDIM + n0 + seg * 8) = v;
            }
        }
    } else {
#pragma unroll
        for (int mi = 0; mi < 4; mi++) {
#pragma unroll
            for (int half = 0; half < 2; half++) {
                int rl = wm * 64 + mi * 16 + gid + half * 8;
                if (m0 + rl < cnt) {
                    int pr = sPair[rl];
                    float wgt  = sW[rl];
                    __half* dst = g_yh + (size_t)pr * CDIM;
#pragma unroll
                    for (int ni = 0; ni < 4; ni++) {
                        int n = n0 + wn * 32 + ni * 8 + 2 * tig;
                        float v0 = wgt * (acc[mi][ni][half * 2 + 0] + bptr[n]);
                        float v1 = wgt * (acc[mi][ni][half * 2 + 1] + bptr[n + 1]);
                        *reinterpret_cast<__half2*>(dst + n) = __floats2half2_rn(v0, v1);
                    }
                }
            }
        }
    }
}

// ---------------- kernel: combine pairs (fp16) -> out (fp32) ----------------
__global__ void combine_kernel(float* __restrict__ out) {
    int i = blockIdx.x * blockDim.x + threadIdx.x;   // over NTOK * CDIM/8
    const int n8 = NTOK * (CDIM / 8);
    if (i >= n8) return;
    int t = i / (CDIM / 8), c = i % (CDIM / 8);
    uint4 a8 = ((const uint4*)(g_yh + (size_t)(2 * t) * CDIM))[c];
    uint4 b8 = ((const uint4*)(g_yh + (size_t)(2 * t + 1) * CDIM))[c];
    const __half2* ah = reinterpret_cast<const __half2*>(&a8);
    const __half2* bh = reinterpret_cast<const __half2*>(&b8);
    float4 o0, o1;
    {
        float2 a0 = __half22float2(ah[0]), b0 = __half22float2(bh[0]);
        float2 a1 = __half22float2(ah[1]), b1 = __half22float2(bh[1]);
        o0.x = a0.x + b0.x; o0.y = a0.y + b0.y;
        o0.z = a1.x + b1.x; o0.w = a1.y + b1.y;
        float2 a2 = __half22float2(ah[2]), b2 = __half22float2(bh[2]);
        float2 a3 = __half22float2(ah[3]), b3 = __half22float2(bh[3]);
        o1.x = a2.x + b2.x; o1.y = a2.y + b2.y;
        o1.z = a3.x + b3.x; o1.w = a3.y + b3.y;
    }
    ((float4*)out)[i * 2]     = o0;
    ((float4*)out)[i * 2 + 1] = o1;
}

// ---------------- launch ----------------
extern "C" void kernel_launch(void* const* d_in, const int* in_sizes, int n_in,
                              void* d_out, int out_size) {
    (void)in_sizes; (void)n_in; (void)out_size;
    const float* x  = (const float*)d_in[0];
    const float* rw = (const float*)d_in[1];
    const float* w1 = (const float*)d_in[2];
    const float* b1 = (const float*)d_in[3];
    const float* w2 = (const float*)d_in[4];
    const float* b2 = (const float*)d_in[5];
    float* out = (float*)d_out;

    cudaFuncSetAttribute(moe_gemm<1>, cudaFuncAttributeMaxDynamicSharedMemorySize, SMEM_DYN);
    cudaFuncSetAttribute(moe_gemm<2>, cudaFuncAttributeMaxDynamicSharedMemorySize, SMEM_DYN);

    init_kernel<<<1, 32>>>();
    prolog_kernel<<<PRO_RTR + PRO_T1 + PRO_T2, 256>>>(x, rw, w1, w2);

    moe_gemm<1><<<dim3(FDIM / BN, NTOK / BM, NEXP), 256, SMEM_DYN>>>(b1);
    moe_gemm<2><<<dim3(CDIM / BN, NTOK / BM, NEXP), 256, SMEM_DYN>>>(b2);

    combine_kernel<<<(NTOK * (CDIM / 8) + 255) / 256, 256>>>(out);
}

// round 15
// speedup vs baseline: 1.0171x; 1.0021x over previous
#include <cuda_runtime.h>
#include <cuda_fp16.h>
#include <math.h>
#include <stdint.h>

// ---------------- problem constants ----------------
#define NTOK  16384
#define CDIM  768
#define FDIM  3072
#define NEXP  8
#define NPAIR (NTOK * 2)
#define MAXTILES 264                      // sum ceil(cnt_e/128) <= 256 + 8

// ---------------- scratch (static device arrays) ----------------
__device__ int    g_count[NEXP];
__device__ int    g_bucket[NEXP * NTOK];
__device__ float  g_wt[NPAIR];
__device__ int    g_tile_e[MAXTILES];
__device__ int    g_tile_m[MAXTILES];
__device__ int    g_ntiles;
__device__ __half g_xh[(size_t)NTOK * CDIM];          // x in fp16
__device__ __half g_w1t[(size_t)NEXP * FDIM * CDIM];  // w1^T fp16 [E][F][C] (K contig)
__device__ __half g_w2t[(size_t)NEXP * CDIM * FDIM];  // w2^T fp16 [E][C][F]
__device__ __half g_h[(size_t)NPAIR * FDIM];          // gelu(x@w1+b1) fp16
__device__ __half g_yh[(size_t)NPAIR * CDIM];         // w*(h@w2+b2) per pair, fp16

// ---------------- helpers ----------------
__device__ __forceinline__ float gelu_f(float x) {
    return 0.5f * x * (1.0f + erff(x * 0.70710678118654752440f));
}
__device__ __forceinline__ uint32_t sw128(uint32_t o) { return o ^ ((o >> 3) & 0x70); }

__device__ __forceinline__ void cp16s(uint32_t saddr, const void* g) {
    asm volatile("cp.async.cg.shared.global [%0], [%1], 16;" :: "r"(saddr), "l"(g));
}

__device__ __forceinline__ void ldm_x4(uint32_t r[4], uint32_t addr) {
    asm volatile("ldmatrix.sync.aligned.m8n8.x4.shared.b16 {%0,%1,%2,%3}, [%4];"
                 : "=r"(r[0]), "=r"(r[1]), "=r"(r[2]), "=r"(r[3]) : "r"(addr));
}

__device__ __forceinline__ void mma16816(float c[4], const uint32_t a[4], const uint32_t* b) {
    asm volatile(
        "mma.sync.aligned.m16n8k16.row.col.f32.f16.f16.f32 "
        "{%0,%1,%2,%3},{%4,%5,%6,%7},{%8,%9},{%0,%1,%2,%3};"
        : "+f"(c[0]), "+f"(c[1]), "+f"(c[2]), "+f"(c[3])
        : "r"(a[0]), "r"(a[1]), "r"(a[2]), "r"(a[3]), "r"(b[0]), "r"(b[1]));
}

// ---------------- kernel: init ----------------
__global__ void init_kernel() {
    if (threadIdx.x < NEXP) g_count[threadIdx.x] = 0;
}

// ---------------- kernel: build compacted tile table ----------------
__global__ void build_tiles() {
    if (threadIdx.x == 0) {
        int t = 0;
        for (int e = 0; e < NEXP; e++) {
            int nt = (g_count[e] + 127) / 128;
            for (int m = 0; m < nt; m++) { g_tile_e[t] = e; g_tile_m[t] = m; t++; }
        }
        g_ntiles = t;
    }
}

// ---------------- kernel: fused prolog ----------------
// blocks [0, 2048)      : router + x->fp16 conversion
// blocks [2048, 6656)   : transpose w1 -> g_w1t  (R=CDIM, S=FDIM)
// blocks [6656, 11264)  : transpose w2 -> g_w2t  (R=FDIM, S=CDIM)
#define PRO_RTR  2048
#define PRO_T1   4608
#define PRO_T2   4608

__device__ __forceinline__ void transpose_body(
    const float* __restrict__ I, __half* __restrict__ O,
    int R, int S, int s0, int r0, float* tile /* [32][129] */, int tid)
{
    int tx = tid & 31, ty = tid >> 5;
#pragma unroll
    for (int k = 0; k < 16; k++) {
        int row = ty + 8 * k;
        tile[tx * 129 + row] = I[(size_t)(r0 + row) * S + s0 + tx];
    }
    __syncthreads();
    int rr = (tid & 63) * 2;
#pragma unroll
    for (int k = 0; k < 8; k++) {
        int sy = (tid >> 6) + 4 * k;
        __half2 h2 = __floats2half2_rn(tile[sy * 129 + rr], tile[sy * 129 + rr + 1]);
        *reinterpret_cast<__half2*>(O + (size_t)(s0 + sy) * R + r0 + rr) = h2;
    }
}

__global__ void prolog_kernel(const float* __restrict__ x,  const float* __restrict__ rw,
                              const float* __restrict__ w1, const float* __restrict__ w2) {
    __shared__ float smem[NEXP * CDIM];
    const int b   = blockIdx.x;
    const int tid = threadIdx.x;

    if (b < PRO_RTR) {
        for (int j = tid; j < NEXP * CDIM; j += 256) smem[j] = rw[j];
        __syncthreads();

        int warp = tid >> 5, lane = tid & 31;
        int t = b * 8 + warp;

        float xv[24];
#pragma unroll
        for (int j = 0; j < 24; j++) xv[j] = x[(size_t)t * CDIM + lane + 32 * j];
#pragma unroll
        for (int j = 0; j < 24; j++)
            g_xh[(size_t)t * CDIM + lane + 32 * j] = __float2half(xv[j]);

        float logit[NEXP];
#pragma unroll
        for (int e = 0; e < NEXP; e++) {
            float s = 0.0f;
#pragma unroll
            for (int j = 0; j < 24; j++) s += xv[j] * smem[e * CDIM + lane + 32 * j];
#pragma unroll
            for (int o = 16; o > 0; o >>= 1) s += __shfl_xor_sync(0xffffffffu, s, o);
            logit[e] = s;
        }

        if (lane == 0) {
            int e0 = 0; float l0 = logit[0];
#pragma unroll
            for (int e = 1; e < NEXP; e++)
                if (logit[e] > l0) { l0 = logit[e]; e0 = e; }
            int e1 = (e0 == 0) ? 1 : 0; float l1 = logit[e1];
#pragma unroll
            for (int e = 0; e < NEXP; e++)
                if (e != e0 && logit[e] > l1) { l1 = logit[e]; e1 = e; }

            float d = expf(l1 - l0);
            float w0 = 1.0f / (1.0f + d);
            float w1w = d / (1.0f + d);

            int p0 = 2 * t, p1 = 2 * t + 1;
            g_wt[p0] = w0;
            g_wt[p1] = w1w;
            int pos0 = atomicAdd(&g_count[e0], 1);
            g_bucket[e0 * NTOK + pos0] = p0;
            int pos1 = atomicAdd(&g_count[e1], 1);
            g_bucket[e1 * NTOK + pos1] = p1;
        }
    } else if (b < PRO_RTR + PRO_T1) {
        int bb = b - PRO_RTR;
        int sx = bb % (FDIM / 32);
        int ry = (bb / (FDIM / 32)) % (CDIM / 128);
        int e  = bb / ((FDIM / 32) * (CDIM / 128));
        transpose_body(w1 + (size_t)e * CDIM * FDIM, g_w1t + (size_t)e * CDIM * FDIM,
                       CDIM, FDIM, sx * 32, ry * 128, smem, tid);
    } else {
        int bb = b - PRO_RTR - PRO_T1;
        int sx = bb % (CDIM / 32);
        int ry = (bb / (CDIM / 32)) % (FDIM / 128);
        int e  = bb / ((CDIM / 32) * (FDIM / 128));
        transpose_body(w2 + (size_t)e * FDIM * CDIM, g_w2t + (size_t)e * FDIM * CDIM,
                       FDIM, CDIM, sx * 32, ry * 128, smem, tid);
    }
}

// ---------------- fp16 HMMA MoE GEMM (frozen mainloop, compacted grid) -----
// PHASE 1: g_h[pair]  = gelu(x[tok] @ w1[e] + b1[e])      (K=768,  N=3072)
// PHASE 2: g_yh[pair] = w_pair * (g_h[pair] @ w2[e] + b2) (K=3072, N=768)
#define BM   128
#define BN   128
#define BKH  64
#define NST  3
#define A_BYTES (BM * 128)
#define B_BYTES (BN * 128)
#define STAGE_BYTES (A_BYTES + B_BYTES)   // 32768
#define SMEM_DYN (NST * STAGE_BYTES + 1024)
#define EPI_STRIDE 272

template <int PHASE>
__global__ void __launch_bounds__(256, 2) moe_gemm(const float* __restrict__ bias) {
    constexpr int KD = (PHASE == 1) ? CDIM : FDIM;
    constexpr int ND = (PHASE == 1) ? FDIM : CDIM;
    constexpr int KT = KD / BKH;          // 12 or 48

    const int ty = blockIdx.y;
    if (ty >= g_ntiles) return;           // compacted: real tiles contiguous
    const int e   = g_tile_e[ty];
    const int m0  = g_tile_m[ty] * BM;
    const int cnt = g_count[e];
    const int n0  = blockIdx.x * BN;

    extern __shared__ char dsm[];
    uint32_t sb0;
    asm("{ .reg .u64 t; cvta.to.shared.u64 t, %1; cvt.u32.u64 %0, t; }" : "=r"(sb0) : "l"(dsm));
    const uint32_t sbase = (sb0 + 1023) & ~1023u;
    char* smal = dsm + (sbase - sb0);

    __shared__ int   sPair[BM];
    __shared__ float sW[BM];

    const int tid  = threadIdx.x;
    const int wid  = tid >> 5;
    const int lane = tid & 31;

    if (tid < BM) {
        int pr = g_bucket[e * NTOK + min(m0 + tid, cnt - 1)];
        sPair[tid] = pr;
        sW[tid] = g_wt[pr];
    }
    __syncthreads();

    const __half* Ag = (PHASE == 1) ? g_xh : g_h;
    const __half* We = ((PHASE == 1) ? g_w1t : g_w2t)
                       + (size_t)e * KD * ND + (size_t)n0 * KD;

    // ---- per-thread precomputed copy sources / swizzled dests ----
    const int crow = tid >> 3, cch = tid & 7;
    const __half* aSrc[4]; const __half* bSrc[4];
    uint32_t aDst[4], bDst[4];
#pragma unroll
    for (int q = 0; q < 4; q++) {
        int r = crow + q * 32;
        int pr = sPair[r];
        aSrc[q] = Ag + ((PHASE == 1) ? (size_t)(pr >> 1) * CDIM : (size_t)pr * FDIM) + cch * 8;
        bSrc[q] = We + (size_t)r * KD + cch * 8;
        aDst[q] = sw128((uint32_t)(r * 128 + cch * 16));
        bDst[q] = sw128((uint32_t)(r * 128 + cch * 16)) + A_BYTES;
    }

    auto load_chunk = [&](int kt) {
        const uint32_t base = sbase + (kt % NST) * STAGE_BYTES;
        const int koff = kt * BKH;
#pragma unroll
        for (int q = 0; q < 4; q++) cp16s(base + aDst[q], aSrc[q] + koff);
#pragma unroll
        for (int q = 0; q < 4; q++) cp16s(base + bDst[q], bSrc[q] + koff);
        asm volatile("cp.async.commit_group;");
    };

    // ---- per-thread ldmatrix address precompute ----
    const int wm = wid >> 2, wn = wid & 3;
    const int ahi = lane >> 4;
    const int bhi = (lane >> 3) & 1;
    uint32_t arel[4]; int axr[4];
#pragma unroll
    for (int mi = 0; mi < 4; mi++) {
        int r = wm * 64 + mi * 16 + (lane & 15);
        arel[mi] = r * 128;
        axr[mi] = r & 7;
    }
    uint32_t brel[2]; int bxr[2];
#pragma unroll
    for (int nj = 0; nj < 2; nj++) {
        int r = wn * 32 + nj * 16 + ((lane >> 4) << 3) + (lane & 7);
        brel[nj] = r * 128;
        bxr[nj] = r & 7;
    }

    float acc[4][4][4];
#pragma unroll
    for (int i = 0; i < 4; i++)
#pragma unroll
        for (int j = 0; j < 4; j++)
#pragma unroll
            for (int r = 0; r < 4; r++) acc[i][j][r] = 0.0f;

    load_chunk(0);
    load_chunk(1);

#pragma unroll 1
    for (int kt = 0; kt < KT; kt++) {
        if (kt + 2 < KT) asm volatile("cp.async.wait_group 1;");
        else             asm volatile("cp.async.wait_group 0;");
        __syncthreads();

        const uint32_t ab = sbase + (kt % NST) * STAGE_BYTES;
        const uint32_t bb = ab + A_BYTES;
        // ks = 0 first: tensor pipe starts immediately after the barrier;
        // next chunk's loads are issued in ks=0's MMA shadow.
#pragma unroll
        for (int ks = 0; ks < 4; ks++) {
            uint32_t a[4][4], b[2][4];
#pragma unroll
            for (int mi = 0; mi < 4; mi++)
                ldm_x4(a[mi], ab + arel[mi] + ((uint32_t)((ks * 2 + ahi) ^ axr[mi]) << 4));
#pragma unroll
            for (int nj = 0; nj < 2; nj++)
                ldm_x4(b[nj], bb + brel[nj] + ((uint32_t)((ks * 2 + bhi) ^ bxr[nj]) << 4));
#pragma unroll
            for (int mi = 0; mi < 4; mi++)
#pragma unroll
                for (int ni = 0; ni < 4; ni++)
                    mma16816(acc[mi][ni], a[mi], &b[ni >> 1][(ni & 1) * 2]);
            if (ks == 0 && kt + 2 < KT) load_chunk(kt + 2);
        }
    }

    // ---------------- epilogue ----------------
    const int gid = lane >> 2, tig = lane & 3;
    const float* bptr = bias + (size_t)e * ND;

    if (PHASE == 1) {
#pragma unroll
        for (int mi = 0; mi < 4; mi++) {
#pragma unroll
            for (int half = 0; half < 2; half++) {
                int rl = wm * 64 + mi * 16 + gid + half * 8;
                char* rowp = smal + rl * EPI_STRIDE;
#pragma unroll
                for (int ni = 0; ni < 4; ni++) {
                    int cl = wn * 32 + ni * 8 + 2 * tig;
                    int n  = n0 + cl;
                    float v0 = gelu_f(acc[mi][ni][half * 2 + 0] + bptr[n]);
                    float v1 = gelu_f(acc[mi][ni][half * 2 + 1] + bptr[n + 1]);
                    *reinterpret_cast<__half2*>(rowp + cl * 2) = __floats2half2_rn(v0, v1);
                }
            }
        }
        __syncthreads();
#pragma unroll
        for (int k = 0; k < 8; k++) {
            int id  = tid + k * 256;
            int row = id >> 4, seg = id & 15;
            if (m0 + row < cnt) {
                uint4 v = *reinterpret_cast<uint4*>(smal + row * EPI_STRIDE + seg * 16);
                int pr = sPair[row];
                *reinterpret_cast<uint4*>(g_h + (size_t)pr * FDIM + n0 + seg * 8) = v;
            }
        }
    } else {
#pragma unroll
        for (int mi = 0; mi < 4; mi++) {
#pragma unroll
            for (int half = 0; half < 2; half++) {
                int rl = wm * 64 + mi * 16 + gid + half * 8;
                if (m0 + rl < cnt) {
                    int pr = sPair[rl];
                    float wgt  = sW[rl];
                    __half* dst = g_yh + (size_t)pr * CDIM;
#pragma unroll
                    for (int ni = 0; ni < 4; ni++) {
                        int n = n0 + wn * 32 + ni * 8 + 2 * tig;
                        float v0 = wgt * (acc[mi][ni][half * 2 + 0] + bptr[n]);
                        float v1 = wgt * (acc[mi][ni][half * 2 + 1] + bptr[n + 1]);
                        *reinterpret_cast<__half2*>(dst + n) = __floats2half2_rn(v0, v1);
                    }
                }
            }
        }
    }
}

// ---------------- kernel: combine pairs (fp16) -> out (fp32) ----------------
__global__ void combine_kernel(float* __restrict__ out) {
    int i = blockIdx.x * blockDim.x + threadIdx.x;
    const int n8 = NTOK * (CDIM / 8);
    if (i >= n8) return;
    int t = i / (CDIM / 8), c = i % (CDIM / 8);
    uint4 a8 = ((const uint4*)(g_yh + (size_t)(2 * t) * CDIM))[c];
    uint4 b8 = ((const uint4*)(g_yh + (size_t)(2 * t + 1) * CDIM))[c];
    const __half2* ah = reinterpret_cast<const __half2*>(&a8);
    const __half2* bh = reinterpret_cast<const __half2*>(&b8);
    float4 o0, o1;
    {
        float2 a0 = __half22float2(ah[0]), b0 = __half22float2(bh[0]);
        float2 a1 = __half22float2(ah[1]), b1 = __half22float2(bh[1]);
        o0.x = a0.x + b0.x; o0.y = a0.y + b0.y;
        o0.z = a1.x + b1.x; o0.w = a1.y + b1.y;
        float2 a2 = __half22float2(ah[2]), b2 = __half22float2(bh[2]);
        float2 a3 = __half22float2(ah[3]), b3 = __half22float2(bh[3]);
        o1.x = a2.x + b2.x; o1.y = a2.y + b2.y;
        o1.z = a3.x + b3.x; o1.w = a3.y + b3.y;
    }
    ((float4*)out)[i * 2]     = o0;
    ((float4*)out)[i * 2 + 1] = o1;
}

// ---------------- launch ----------------
extern "C" void kernel_launch(void* const* d_in, const int* in_sizes, int n_in,
                              void* d_out, int out_size) {
    (void)in_sizes; (void)n_in; (void)out_size;
    const float* x  = (const float*)d_in[0];
    const float* rw = (const float*)d_in[1];
    const float* w1 = (const float*)d_in[2];
    const float* b1 = (const float*)d_in[3];
    const float* w2 = (const float*)d_in[4];
    const float* b2 = (const float*)d_in[5];
    float* out = (float*)d_out;

    cudaFuncSetAttribute(moe_gemm<1>, cudaFuncAttributeMaxDynamicSharedMemorySize, SMEM_DYN);
    cudaFuncSetAttribute(moe_gemm<2>, cudaFuncAttributeMaxDynamicSharedMemorySize, SMEM_DYN);

    init_kernel<<<1, 32>>>();
    prolog_kernel<<<PRO_RTR + PRO_T1 + PRO_T2, 256>>>(x, rw, w1, w2);
    build_tiles<<<1, 32>>>();

    moe_gemm<1><<<dim3(FDIM / BN, MAXTILES), 256, SMEM_DYN>>>(b1);
    moe_gemm<2><<<dim3(CDIM / BN, MAXTILES), 256, SMEM_DYN>>>(b2);

    combine_kernel<<<(NTOK * (CDIM / 8) + 255) / 256, 256>>>(out);
}

// round 17
// speedup vs baseline: 1.0759x; 1.0578x over previous
#include <cuda_runtime.h>
#include <cuda_fp16.h>
#include <math.h>
#include <stdint.h>

// ---------------- problem constants ----------------
#define NTOK  16384
#define CDIM  768
#define FDIM  3072
#define NEXP  8
#define NPAIR (NTOK * 2)
#define MAXTILES 264                      // sum ceil(cnt_e/128) <= 256 + 8

// ---------------- scratch (static device arrays) ----------------
__device__ int    g_count[NEXP];
__device__ int    g_bucket[NEXP * NTOK];
__device__ float  g_wt[NPAIR];
__device__ int    g_tile_e[MAXTILES];
__device__ int    g_tile_m[MAXTILES];
__device__ int    g_ntiles;
__device__ __half g_xh[(size_t)NTOK * CDIM];          // x in fp16
__device__ __half g_w1t[(size_t)NEXP * FDIM * CDIM];  // w1^T fp16 [E][F][C] (K contig)
__device__ __half g_w2t[(size_t)NEXP * CDIM * FDIM];  // w2^T fp16 [E][C][F]
__device__ __half g_h[(size_t)NPAIR * FDIM];          // gelu(x@w1+b1) fp16
__device__ __half g_yh[(size_t)NPAIR * CDIM];         // w*(h@w2+b2) per pair, fp16

// ---------------- helpers ----------------
// GELU, tanh form, using HW MUFU.TANH. Formula error is negligible for the
// ~N(0,0.55) pre-activations here (matches exact erf-GELU to x^3 near 0);
// tanh.approx rel err 2^-10.7 adds ~7e-5 RMS to h — same order as the fp16
// quantization of g_h that is already applied.
__device__ __forceinline__ float gelu_f(float x) {
    float inner = 0.7978845608028654f * x * fmaf(0.044715f, x * x, 1.0f);
    float t;
    asm("tanh.approx.f32 %0, %1;" : "=f"(t) : "f"(inner));
    return 0.5f * x * (1.0f + t);
}
__device__ __forceinline__ uint32_t sw128(uint32_t o) { return o ^ ((o >> 3) & 0x70); }

__device__ __forceinline__ void cp16s(uint32_t saddr, const void* g) {
    asm volatile("cp.async.cg.shared.global [%0], [%1], 16;" :: "r"(saddr), "l"(g));
}

__device__ __forceinline__ void ldm_x4(uint32_t r[4], uint32_t addr) {
    asm volatile("ldmatrix.sync.aligned.m8n8.x4.shared.b16 {%0,%1,%2,%3}, [%4];"
                 : "=r"(r[0]), "=r"(r[1]), "=r"(r[2]), "=r"(r[3]) : "r"(addr));
}

__device__ __forceinline__ void mma16816(float c[4], const uint32_t a[4], const uint32_t* b) {
    asm volatile(
        "mma.sync.aligned.m16n8k16.row.col.f32.f16.f16.f32 "
        "{%0,%1,%2,%3},{%4,%5,%6,%7},{%8,%9},{%0,%1,%2,%3};"
        : "+f"(c[0]), "+f"(c[1]), "+f"(c[2]), "+f"(c[3])
        : "r"(a[0]), "r"(a[1]), "r"(a[2]), "r"(a[3]), "r"(b[0]), "r"(b[1]));
}

// ---------------- kernel: init ----------------
__global__ void init_kernel() {
    if (threadIdx.x < NEXP) g_count[threadIdx.x] = 0;
}

// ---------------- kernel: build compacted tile table ----------------
__global__ void build_tiles() {
    if (threadIdx.x == 0) {
        int t = 0;
        for (int e = 0; e < NEXP; e++) {
            int nt = (g_count[e] + 127) / 128;
            for (int m = 0; m < nt; m++) { g_tile_e[t] = e; g_tile_m[t] = m; t++; }
        }
        g_ntiles = t;
    }
}

// ---------------- kernel: fused prolog ----------------
// blocks [0, 2048)      : router + x->fp16 conversion
// blocks [2048, 6656)   : transpose w1 -> g_w1t  (R=CDIM, S=FDIM)
// blocks [6656, 11264)  : transpose w2 -> g_w2t  (R=FDIM, S=CDIM)
#define PRO_RTR  2048
#define PRO_T1   4608
#define PRO_T2   4608

__device__ __forceinline__ void transpose_body(
    const float* __restrict__ I, __half* __restrict__ O,
    int R, int S, int s0, int r0, float* tile /* [32][129] */, int tid)
{
    int tx = tid & 31, ty = tid >> 5;
#pragma unroll
    for (int k = 0; k < 16; k++) {
        int row = ty + 8 * k;
        tile[tx * 129 + row] = I[(size_t)(r0 + row) * S + s0 + tx];
    }
    __syncthreads();
    int rr = (tid & 63) * 2;
#pragma unroll
    for (int k = 0; k < 8; k++) {
        int sy = (tid >> 6) + 4 * k;
        __half2 h2 = __floats2half2_rn(tile[sy * 129 + rr], tile[sy * 129 + rr + 1]);
        *reinterpret_cast<__half2*>(O + (size_t)(s0 + sy) * R + r0 + rr) = h2;
    }
}

__global__ void prolog_kernel(const float* __restrict__ x,  const float* __restrict__ rw,
                              const float* __restrict__ w1, const float* __restrict__ w2) {
    __shared__ float smem[NEXP * CDIM];
    const int b   = blockIdx.x;
    const int tid = threadIdx.x;

    if (b < PRO_RTR) {
        for (int j = tid; j < NEXP * CDIM; j += 256) smem[j] = rw[j];
        __syncthreads();

        int warp = tid >> 5, lane = tid & 31;
        int t = b * 8 + warp;

        float xv[24];
#pragma unroll
        for (int j = 0; j < 24; j++) xv[j] = x[(size_t)t * CDIM + lane + 32 * j];
#pragma unroll
        for (int j = 0; j < 24; j++)
            g_xh[(size_t)t * CDIM + lane + 32 * j] = __float2half(xv[j]);

        float logit[NEXP];
#pragma unroll
        for (int e = 0; e < NEXP; e++) {
            float s = 0.0f;
#pragma unroll
            for (int j = 0; j < 24; j++) s += xv[j] * smem[e * CDIM + lane + 32 * j];
#pragma unroll
            for (int o = 16; o > 0; o >>= 1) s += __shfl_xor_sync(0xffffffffu, s, o);
            logit[e] = s;
        }

        if (lane == 0) {
            int e0 = 0; float l0 = logit[0];
#pragma unroll
            for (int e = 1; e < NEXP; e++)
                if (logit[e] > l0) { l0 = logit[e]; e0 = e; }
            int e1 = (e0 == 0) ? 1 : 0; float l1 = logit[e1];
#pragma unroll
            for (int e = 0; e < NEXP; e++)
                if (e != e0 && logit[e] > l1) { l1 = logit[e]; e1 = e; }

            float d = expf(l1 - l0);
            float w0 = 1.0f / (1.0f + d);
            float w1w = d / (1.0f + d);

            int p0 = 2 * t, p1 = 2 * t + 1;
            g_wt[p0] = w0;
            g_wt[p1] = w1w;
            int pos0 = atomicAdd(&g_count[e0], 1);
            g_bucket[e0 * NTOK + pos0] = p0;
            int pos1 = atomicAdd(&g_count[e1], 1);
            g_bucket[e1 * NTOK + pos1] = p1;
        }
    } else if (b < PRO_RTR + PRO_T1) {
        int bb = b - PRO_RTR;
        int sx = bb % (FDIM / 32);
        int ry = (bb / (FDIM / 32)) % (CDIM / 128);
        int e  = bb / ((FDIM / 32) * (CDIM / 128));
        transpose_body(w1 + (size_t)e * CDIM * FDIM, g_w1t + (size_t)e * CDIM * FDIM,
                       CDIM, FDIM, sx * 32, ry * 128, smem, tid);
    } else {
        int bb = b - PRO_RTR - PRO_T1;
        int sx = bb % (CDIM / 32);
        int ry = (bb / (CDIM / 32)) % (FDIM / 128);
        int e  = bb / ((CDIM / 32) * (FDIM / 128));
        transpose_body(w2 + (size_t)e * FDIM * CDIM, g_w2t + (size_t)e * FDIM * CDIM,
                       FDIM, CDIM, sx * 32, ry * 128, smem, tid);
    }
}

// ---------------- fp16 HMMA MoE GEMM (frozen mainloop, compacted grid) -----
// PHASE 1: g_h[pair]  = gelu(x[tok] @ w1[e] + b1[e])      (K=768,  N=3072)
// PHASE 2: g_yh[pair] = w_pair * (g_h[pair] @ w2[e] + b2) (K=3072, N=768)
#define BM   128
#define BN   128
#define BKH  64
#define NST  3
#define A_BYTES (BM * 128)
#define B_BYTES (BN * 128)
#define STAGE_BYTES (A_BYTES + B_BYTES)   // 32768
#define SMEM_DYN (NST * STAGE_BYTES + 1024)
#define EPI_STRIDE 272

template <int PHASE>
__global__ void __launch_bounds__(256, 2) moe_gemm(const float* __restrict__ bias) {
    constexpr int KD = (PHASE == 1) ? CDIM : FDIM;
    constexpr int ND = (PHASE == 1) ? FDIM : CDIM;
    constexpr int KT = KD / BKH;          // 12 or 48

    const int ty = blockIdx.y;
    if (ty >= g_ntiles) return;           // compacted: real tiles contiguous
    const int e   = g_tile_e[ty];
    const int m0  = g_tile_m[ty] * BM;
    const int cnt = g_count[e];
    const int n0  = blockIdx.x * BN;

    extern __shared__ char dsm[];
    uint32_t sb0;
    asm("{ .reg .u64 t; cvta.to.shared.u64 t, %1; cvt.u32.u64 %0, t; }" : "=r"(sb0) : "l"(dsm));
    const uint32_t sbase = (sb0 + 1023) & ~1023u;
    char* smal = dsm + (sbase - sb0);

    __shared__ int   sPair[BM];
    __shared__ float sW[BM];

    const int tid  = threadIdx.x;
    const int wid  = tid >> 5;
    const int lane = tid & 31;

    if (tid < BM) {
        int pr = g_bucket[e * NTOK + min(m0 + tid, cnt - 1)];
        sPair[tid] = pr;
        sW[tid] = g_wt[pr];
    }
    __syncthreads();

    const __half* Ag = (PHASE == 1) ? g_xh : g_h;
    const __half* We = ((PHASE == 1) ? g_w1t : g_w2t)
                       + (size_t)e * KD * ND + (size_t)n0 * KD;

    // ---- per-thread precomputed copy sources / swizzled dests ----
    const int crow = tid >> 3, cch = tid & 7;
    const __half* aSrc[4]; const __half* bSrc[4];
    uint32_t aDst[4], bDst[4];
#pragma unroll
    for (int q = 0; q < 4; q++) {
        int r = crow + q * 32;
        int pr = sPair[r];
        aSrc[q] = Ag + ((PHASE == 1) ? (size_t)(pr >> 1) * CDIM : (size_t)pr * FDIM) + cch * 8;
        bSrc[q] = We + (size_t)r * KD + cch * 8;
        aDst[q] = sw128((uint32_t)(r * 128 + cch * 16));
        bDst[q] = sw128((uint32_t)(r * 128 + cch * 16)) + A_BYTES;
    }

    auto load_chunk = [&](int kt) {
        const uint32_t base = sbase + (kt % NST) * STAGE_BYTES;
        const int koff = kt * BKH;
#pragma unroll
        for (int q = 0; q < 4; q++) cp16s(base + aDst[q], aSrc[q] + koff);
#pragma unroll
        for (int q = 0; q < 4; q++) cp16s(base + bDst[q], bSrc[q] + koff);
        asm volatile("cp.async.commit_group;");
    };

    // ---- per-thread ldmatrix address precompute ----
    const int wm = wid >> 2, wn = wid & 3;
    const int ahi = lane >> 4;
    const int bhi = (lane >> 3) & 1;
    uint32_t arel[4]; int axr[4];
#pragma unroll
    for (int mi = 0; mi < 4; mi++) {
        int r = wm * 64 + mi * 16 + (lane & 15);
        arel[mi] = r * 128;
        axr[mi] = r & 7;
    }
    uint32_t brel[2]; int bxr[2];
#pragma unroll
    for (int nj = 0; nj < 2; nj++) {
        int r = wn * 32 + nj * 16 + ((lane >> 4) << 3) + (lane & 7);
        brel[nj] = r * 128;
        bxr[nj] = r & 7;
    }

    float acc[4][4][4];
#pragma unroll
    for (int i = 0; i < 4; i++)
#pragma unroll
        for (int j = 0; j < 4; j++)
#pragma unroll
            for (int r = 0; r < 4; r++) acc[i][j][r] = 0.0f;

    load_chunk(0);
    load_chunk(1);

#pragma unroll 1
    for (int kt = 0; kt < KT; kt++) {
        if (kt + 2 < KT) asm volatile("cp.async.wait_group 1;");
        else             asm volatile("cp.async.wait_group 0;");
        __syncthreads();

        const uint32_t ab = sbase + (kt % NST) * STAGE_BYTES;
        const uint32_t bb = ab + A_BYTES;
        // ks = 0 first: tensor pipe starts immediately after the barrier;
        // next chunk's loads are issued in ks=0's MMA shadow.
#pragma unroll
        for (int ks = 0; ks < 4; ks++) {
            uint32_t a[4][4], b[2][4];
#pragma unroll
            for (int mi = 0; mi < 4; mi++)
                ldm_x4(a[mi], ab + arel[mi] + ((uint32_t)((ks * 2 + ahi) ^ axr[mi]) << 4));
#pragma unroll
            for (int nj = 0; nj < 2; nj++)
                ldm_x4(b[nj], bb + brel[nj] + ((uint32_t)((ks * 2 + bhi) ^ bxr[nj]) << 4));
#pragma unroll
            for (int mi = 0; mi < 4; mi++)
#pragma unroll
                for (int ni = 0; ni < 4; ni++)
                    mma16816(acc[mi][ni], a[mi], &b[ni >> 1][(ni & 1) * 2]);
            if (ks == 0 && kt + 2 < KT) load_chunk(kt + 2);
        }
    }

    // ---------------- epilogue ----------------
    const int gid = lane >> 2, tig = lane & 3;
    const float* bptr = bias + (size_t)e * ND;

    if (PHASE == 1) {
#pragma unroll
        for (int mi = 0; mi < 4; mi++) {
#pragma unroll
            for (int half = 0; half < 2; half++) {
                int rl = wm * 64 + mi * 16 + gid + half * 8;
                char* rowp = smal + rl * EPI_STRIDE;
#pragma unroll
                for (int ni = 0; ni < 4; ni++) {
                    int cl = wn * 32 + ni * 8 + 2 * tig;
                    int n  = n0 + cl;
                    float v0 = gelu_f(acc[mi][ni][half * 2 + 0] + bptr[n]);
                    float v1 = gelu_f(acc[mi][ni][half * 2 + 1] + bptr[n + 1]);
                    *reinterpret_cast<__half2*>(rowp + cl * 2) = __floats2half2_rn(v0, v1);
                }
            }
        }
        __syncthreads();
#pragma unroll
        for (int k = 0; k < 8; k++) {
            int id  = tid + k * 256;
            int row = id >> 4, seg = id & 15;
            if (m0 + row < cnt) {
                uint4 v = *reinterpret_cast<uint4*>(smal + row * EPI_STRIDE + seg * 16);
                int pr = sPair[row];
                *reinterpret_cast<uint4*>(g_h + (size_t)pr * FDIM + n0 + seg * 8) = v;
            }
        }
    } else {
#pragma unroll
        for (int mi = 0; mi < 4; mi++) {
#pragma unroll
            for (int half = 0; half < 2; half++) {
                int rl = wm * 64 + mi * 16 + gid + half * 8;
                if (m0 + rl < cnt) {
                    int pr = sPair[rl];
                    float wgt  = sW[rl];
                    __half* dst = g_yh + (size_t)pr * CDIM;
#pragma unroll
                    for (int ni = 0; ni < 4; ni++) {
                        int n = n0 + wn * 32 + ni * 8 + 2 * tig;
                        float v0 = wgt * (acc[mi][ni][half * 2 + 0] + bptr[n]);
                        float v1 = wgt * (acc[mi][ni][half * 2 + 1] + bptr[n + 1]);
                        *reinterpret_cast<__half2*>(dst + n) = __floats2half2_rn(v0, v1);
                    }
                }
            }
        }
    }
}

// ---------------- kernel: combine pairs (fp16) -> out (fp32) ----------------
__global__ void combine_kernel(float* __restrict__ out) {
    int i = blockIdx.x * blockDim.x + threadIdx.x;
    const int n8 = NTOK * (CDIM / 8);
    if (i >= n8) return;
    int t = i / (CDIM / 8), c = i % (CDIM / 8);
    uint4 a8 = ((const uint4*)(g_yh + (size_t)(2 * t) * CDIM))[c];
    uint4 b8 = ((const uint4*)(g_yh + (size_t)(2 * t + 1) * CDIM))[c];
    const __half2* ah = reinterpret_cast<const __half2*>(&a8);
    const __half2* bh = reinterpret_cast<const __half2*>(&b8);
    float4 o0, o1;
    {
        float2 a0 = __half22float2(ah[0]), b0 = __half22float2(bh[0]);
        float2 a1 = __half22float2(ah[1]), b1 = __half22float2(bh[1]);
        o0.x = a0.x + b0.x; o0.y = a0.y + b0.y;
        o0.z = a1.x + b1.x; o0.w = a1.y + b1.y;
        float2 a2 = __half22float2(ah[2]), b2 = __half22float2(bh[2]);
        float2 a3 = __half22float2(ah[3]), b3 = __half22float2(bh[3]);
        o1.x = a2.x + b2.x; o1.y = a2.y + b2.y;
        o1.z = a3.x + b3.x; o1.w = a3.y + b3.y;
    }
    ((float4*)out)[i * 2]     = o0;
    ((float4*)out)[i * 2 + 1] = o1;
}

// ---------------- launch ----------------
extern "C" void kernel_launch(void* const* d_in, const int* in_sizes, int n_in,
                              void* d_out, int out_size) {
    (void)in_sizes; (void)n_in; (void)out_size;
    const float* x  = (const float*)d_in[0];
    const float* rw = (const float*)d_in[1];
    const float* w1 = (const float*)d_in[2];
    const float* b1 = (const float*)d_in[3];
    const float* w2 = (const float*)d_in[4];
    const float* b2 = (const float*)d_in[5];
    float* out = (float*)d_out;

    cudaFuncSetAttribute(moe_gemm<1>, cudaFuncAttributeMaxDynamicSharedMemorySize, SMEM_DYN);
    cudaFuncSetAttribute(moe_gemm<2>, cudaFuncAttributeMaxDynamicSharedMemorySize, SMEM_DYN);

    init_kernel<<<1, 32>>>();
    prolog_kernel<<<PRO_RTR + PRO_T1 + PRO_T2, 256>>>(x, rw, w1, w2);
    build_tiles<<<1, 32>>>();

    moe_gemm<1><<<dim3(FDIM / BN, MAXTILES), 256, SMEM_DYN>>>(b1);
    moe_gemm<2><<<dim3(CDIM / BN, MAXTILES), 256, SMEM_DYN>>>(b2);

    combine_kernel<<<(NTOK * (CDIM / 8) + 255) / 256, 256>>>(out);
}